// round 7
// baseline (speedup 1.0000x reference)
#include <cuda_runtime.h>
#include <cuda_bf16.h>
#include <float.h>
#include <cstdint>

// Problem constants
#define BB 32
#define SS 2048
#define DD 1024
#define EE 16
#define KK 4
#define OO 1024
#define KD 4096   // KK*DD
#define SPLIT 4

typedef unsigned long long ULL;

// ---------------- scratch (device globals) ----------------
__device__ float g_logits[BB * EE * SS];            // [B][E][S], 4 MB
__device__ float g_wgt[EE * DD];                    // Wg transposed [e][k], 64 KB
__device__ __nv_bfloat16 g_inph[EE * BB * KD];      // inp hi, [e][b][4096]
__device__ __nv_bfloat16 g_inpl[EE * BB * KD];      // inp lo
__device__ __nv_bfloat16 g_h1h[EE * BB * OO];
__device__ __nv_bfloat16 g_h1l[EE * BB * OO];
__device__ __nv_bfloat16 g_h2h[EE * BB * OO];
__device__ __nv_bfloat16 g_h2l[EE * BB * OO];
__device__ float g_part[SPLIT * EE * BB * OO];      // split-K partials, 8 MB

// ---------------- f32x2 helpers ----------------
__device__ __forceinline__ void fma2(ULL& d, ULL a, ULL b) {
    asm("fma.rn.f32x2 %0, %1, %2, %0;" : "+l"(d) : "l"(a), "l"(b));
}
__device__ __forceinline__ float2 unpack2(ULL v) {
    float2 f; asm("mov.b64 {%0, %1}, %2;" : "=f"(f.x), "=f"(f.y) : "l"(v)); return f;
}

// ---------------- bf16 split helper ----------------
__device__ __forceinline__ void split2(float a, float b, uint32_t& hi, uint32_t& lo) {
    asm("cvt.rn.satfinite.bf16x2.f32 %0, %1, %2;" : "=r"(hi) : "f"(b), "f"(a));
    __nv_bfloat162 hp = *reinterpret_cast<__nv_bfloat162*>(&hi);
    float r0 = a - __low2float(hp);
    float r1 = b - __high2float(hp);
    asm("cvt.rn.satfinite.bf16x2.f32 %0, %1, %2;" : "=r"(lo) : "f"(r1), "f"(r0));
}

// ---------------- portable tensor-core / async helpers ----------------
__device__ __forceinline__ uint32_t smem_u32(const void* p) {
    uint32_t a;
    asm("{ .reg .u64 t; cvta.to.shared.u64 t, %1; cvt.u32.u64 %0, t; }" : "=r"(a) : "l"(p));
    return a;
}
__device__ __forceinline__ void ldsm4(uint32_t& r0, uint32_t& r1, uint32_t& r2, uint32_t& r3, uint32_t addr) {
    asm volatile("ldmatrix.sync.aligned.m8n8.x4.shared.b16 {%0,%1,%2,%3}, [%4];"
        : "=r"(r0), "=r"(r1), "=r"(r2), "=r"(r3) : "r"(addr));
}
__device__ __forceinline__ void mma16816(float* c, uint32_t a0, uint32_t a1, uint32_t a2, uint32_t a3,
                                         uint32_t b0, uint32_t b1) {
    asm("mma.sync.aligned.m16n8k16.row.col.f32.bf16.bf16.f32 "
        "{%0,%1,%2,%3}, {%4,%5,%6,%7}, {%8,%9}, {%0,%1,%2,%3};"
        : "+f"(c[0]), "+f"(c[1]), "+f"(c[2]), "+f"(c[3])
        : "r"(a0), "r"(a1), "r"(a2), "r"(a3), "r"(b0), "r"(b1));
}
__device__ __forceinline__ void cp16(uint32_t smem_dst, const void* gsrc) {
    asm volatile("cp.async.cg.shared.global [%0], [%1], 16;" :: "r"(smem_dst), "l"(gsrc));
}
#define CP_COMMIT() asm volatile("cp.async.commit_group;" ::: "memory")
#define CP_WAIT2()  asm volatile("cp.async.wait_group 2;" ::: "memory")
#define CP_WAIT1()  asm volatile("cp.async.wait_group 1;" ::: "memory")
#define CP_WAIT0()  asm volatile("cp.async.wait_group 0;" ::: "memory")

// ---------------- 0) Wg transpose: g_wgt[e][k] = Wg[k][e] ----------------
__global__ void wg_transpose(const float* __restrict__ Wg) {
    int e = blockIdx.x;
    for (int k = threadIdx.x; k < DD; k += 256)
        g_wgt[e * DD + k] = Wg[(size_t)k * EE + e];
}

// ---------------- 1) gate GEMM: cp.async 4-stage, f32x2 packed over K ------
// CTA: 128 tokens x 16 experts, 256 threads. logits[B,E,S] = (x @ Wg + bg)^T
#define GST 4
#define XROW 36                          // floats per token row (32 + 4 pad)
#define XS_BYTES (128 * XROW * 4)        // 18432 per stage
#define WG_ROW 36
#define WGS_BYTES (EE * WG_ROW * 4)      // 2304 per stage
#define GATE_SM (GST * (XS_BYTES + WGS_BYTES))   // 82944

__global__ void __launch_bounds__(256) gate_kernel(const float* __restrict__ x,
                                                   const float* __restrict__ bg) {
    extern __shared__ __align__(16) uint8_t gsm[];
    uint8_t* xs  = gsm;                       // [GST][128][XROW] floats
    uint8_t* wgs = gsm + GST * XS_BYTES;      // [GST][EE][WG_ROW] floats

    int tid = threadIdx.x;
    int t0 = blockIdx.x * 128;
    int b  = t0 >> 11;
    int s0 = t0 & 2047;

    // staging maps
    int stok = tid >> 1;                  // token 0..127
    int shalf = (tid & 1) * 16;           // float col base (16 floats per cp-thread)
    // compute maps
    int tx = tid & 7;                     // e-group
    int ty = tid >> 3;                    // token-group 0..31
    int e0 = tx * 2;
    int m0 = ty * 4;

    ULL acc2[4][2];                       // [token][expert], packed over k-pairs
    #pragma unroll
    for (int i = 0; i < 4; ++i) { acc2[i][0] = 0ULL; acc2[i][1] = 0ULL; }

    const int nch = DD / 32;              // 32 chunks

    auto issue = [&](int c) {
        int slot = c & (GST - 1);
        int k0 = c * 32;
        // x chunk: 128 tokens x 32 floats
        uint32_t xdst = smem_u32(xs + slot * XS_BYTES) + (stok * XROW + shalf) * 4;
        const float* xsrc = &x[(size_t)(t0 + stok) * DD + k0 + shalf];
        #pragma unroll
        for (int i = 0; i < 4; ++i)
            cp16(xdst + i * 16, xsrc + i * 4);
        // Wg chunk (transposed): 16 e x 32 floats = 128 cp16, threads 0..127
        if (tid < 128) {
            int e = tid >> 3, part = tid & 7;
            uint32_t wdst = smem_u32(wgs + slot * WGS_BYTES) + (e * WG_ROW) * 4 + part * 16;
            cp16(wdst, &g_wgt[e * DD + k0 + part * 4]);
        }
        CP_COMMIT();
    };

    issue(0); issue(1); issue(2);

    for (int c = 0; c < nch; ++c) {
        CP_WAIT2();
        __syncthreads();
        if (c + 3 < nch) issue(c + 3);

        int slot = c & (GST - 1);
        const float* xv = (const float*)(xs + slot * XS_BYTES);
        const float* wv = (const float*)(wgs + slot * WGS_BYTES);

        #pragma unroll
        for (int k4 = 0; k4 < 8; ++k4) {
            ulonglong2 wp0 = *(const ulonglong2*)&wv[(e0 + 0) * WG_ROW + k4 * 4];
            ulonglong2 wp1 = *(const ulonglong2*)&wv[(e0 + 1) * WG_ROW + k4 * 4];
            #pragma unroll
            for (int i = 0; i < 4; ++i) {
                ulonglong2 xp = *(const ulonglong2*)&xv[(m0 + i) * XROW + k4 * 4];
                fma2(acc2[i][0], xp.x, wp0.x);
                fma2(acc2[i][0], xp.y, wp0.y);
                fma2(acc2[i][1], xp.x, wp1.x);
                fma2(acc2[i][1], xp.y, wp1.y);
            }
        }
    }

    // epilogue: horizontal add over k-pairs, + bg, float4 store along S
    #pragma unroll
    for (int j = 0; j < 2; ++j) {
        float bb = bg[e0 + j];
        float4 o;
        float2 v0 = unpack2(acc2[0][j]);
        float2 v1 = unpack2(acc2[1][j]);
        float2 v2 = unpack2(acc2[2][j]);
        float2 v3 = unpack2(acc2[3][j]);
        o.x = v0.x + v0.y + bb;
        o.y = v1.x + v1.y + bb;
        o.z = v2.x + v2.y + bb;
        o.w = v3.x + v3.y + bb;
        *(float4*)&g_logits[((size_t)(b * EE) + e0 + j) * SS + s0 + m0] = o;
    }
}

// ---------------- 2) softmax(+top4) + gather (bf16-split output) ----------------
__global__ void topk_gather_kernel(const float* __restrict__ x) {
    int e = blockIdx.x, b = blockIdx.y;
    __shared__ float sv[SS];
    __shared__ float red[256];
    __shared__ int   redi[256];
    __shared__ float s_max, s_sum;
    __shared__ int   s_idx[KK];
    __shared__ float s_val[KK];
    int tid = threadIdx.x;

    const float* row = &g_logits[(size_t)(b * EE + e) * SS];
    float lmax = -FLT_MAX;
    for (int i = tid; i < SS; i += 256) {
        float v = row[i];
        sv[i] = v;
        lmax = fmaxf(lmax, v);
    }
    red[tid] = lmax;
    __syncthreads();
    for (int off = 128; off > 0; off >>= 1) {
        if (tid < off) red[tid] = fmaxf(red[tid], red[tid + off]);
        __syncthreads();
    }
    if (tid == 0) s_max = red[0];
    __syncthreads();
    float mx = s_max;

    float lsum = 0.f;
    for (int i = tid; i < SS; i += 256) lsum += expf(sv[i] - mx);
    red[tid] = lsum;
    __syncthreads();
    for (int off = 128; off > 0; off >>= 1) {
        if (tid < off) red[tid] += red[tid + off];
        __syncthreads();
    }
    if (tid == 0) s_sum = red[0];
    __syncthreads();
    float inv = 1.0f / s_sum;

    for (int it = 0; it < KK; ++it) {
        float bv = -FLT_MAX;
        int bi = SS;
        for (int i = tid; i < SS; i += 256) {
            float v = sv[i];
            if (v > bv) { bv = v; bi = i; }
        }
        red[tid] = bv; redi[tid] = bi;
        __syncthreads();
        for (int off = 128; off > 0; off >>= 1) {
            if (tid < off) {
                float v2 = red[tid + off]; int i2 = redi[tid + off];
                if (v2 > red[tid] || (v2 == red[tid] && i2 < redi[tid])) {
                    red[tid] = v2; redi[tid] = i2;
                }
            }
            __syncthreads();
        }
        if (tid == 0) {
            int wi = redi[0];
            s_idx[it] = wi;
            s_val[it] = expf(red[0] - mx) * inv;
            sv[wi] = -FLT_MAX;
        }
        __syncthreads();
    }

    // gather, scale, bf16-split -> g_inph / g_inpl [e][b][j*D + d]
    #pragma unroll
    for (int j = 0; j < KK; ++j) {
        int idx = s_idx[j];
        float w = s_val[j];
        const float4* src = (const float4*)&x[((size_t)b * SS + idx) * DD];
        __nv_bfloat16* dh = &g_inph[((size_t)(e * BB + b)) * KD + j * DD];
        __nv_bfloat16* dl = &g_inpl[((size_t)(e * BB + b)) * KD + j * DD];
        int d4 = tid;
        float4 v = src[d4];
        v.x *= w; v.y *= w; v.z *= w; v.w *= w;
        uint32_t h0, l0, h1, l1;
        split2(v.x, v.y, h0, l0);
        split2(v.z, v.w, h1, l1);
        *(uint2*)&dh[d4 * 4] = make_uint2(h0, h1);
        *(uint2*)&dl[d4 * 4] = make_uint2(l0, l1);
    }
}

// ---------------- 3) expert GEMM: cp.async 3-stage + mma.sync bf16-split ----
#define STAGES 3
#define A_STRIDE 40                    // bf16 per A row (32 + 8 pad)
#define W_STRIDE 132                   // floats per W row (128 + 4 pad)
#define WS_BYTES (32 * W_STRIDE * 4)   // 16896 per stage
#define AH_BYTES (32 * A_STRIDE * 2)   // 2560 per stage
#define SM_AH_OFF (STAGES * WS_BYTES)
#define SM_AL_OFF (SM_AH_OFF + STAGES * AH_BYTES)
#define SM_TOTAL  (SM_AL_OFF + STAGES * AH_BYTES)   // 66048

template<int MODE>
__global__ void __launch_bounds__(256) expert_mma(const float* __restrict__ W, int Ktot) {
    extern __shared__ __align__(16) uint8_t sm[];

    int e = blockIdx.y, nt = blockIdx.x, ks = blockIdx.z;
    const int Ksub = Ktot / SPLIT;
    const int k0base = ks * Ksub;
    const int nch = Ksub >> 5;

    const __nv_bfloat16 *srcH, *srcL;
    if (MODE == 0)      { srcH = g_inph; srcL = g_inpl; }
    else if (MODE == 1) { srcH = g_h1h;  srcL = g_h1l; }
    else                { srcH = g_h2h;  srcL = g_h2l; }
    const __nv_bfloat16* AHg = srcH + (size_t)e * BB * Ktot;
    const __nv_bfloat16* ALg = srcL + (size_t)e * BB * Ktot;
    const float* We = W + (size_t)e * Ktot * OO + nt * 128;
    float* P = g_part + ((size_t)(ks * EE + e) * BB) * OO + nt * 128;

    int tid = threadIdx.x, lane = tid & 31, wid = tid >> 5;
    int n0 = wid * 16;

    int wrow = tid >> 3;
    int wcol = (tid & 7) * 16;
    int arow = (tid & 127) >> 2;
    int acol = (tid & 3) * 8;

    float acc[2][2][4];
    #pragma unroll
    for (int mt = 0; mt < 2; ++mt)
        #pragma unroll
        for (int nf = 0; nf < 2; ++nf)
            #pragma unroll
            for (int q = 0; q < 4; ++q) acc[mt][nf][q] = 0.f;

    auto issue = [&](int c) {
        int slot = c % STAGES;
        int k0 = k0base + c * 32;
        uint32_t wdst = smem_u32(sm + slot * WS_BYTES) + (wrow * W_STRIDE + wcol) * 4;
        const float* wsrc = &We[(size_t)(k0 + wrow) * OO + wcol];
        #pragma unroll
        for (int i = 0; i < 4; ++i)
            cp16(wdst + i * 16, wsrc + i * 4);
        if (tid < 128) {
            uint32_t adst = smem_u32(sm + SM_AH_OFF + slot * AH_BYTES) + (arow * A_STRIDE + acol) * 2;
            cp16(adst, &AHg[(size_t)arow * Ktot + k0 + acol]);
        } else {
            uint32_t adst = smem_u32(sm + SM_AL_OFF + slot * AH_BYTES) + (arow * A_STRIDE + acol) * 2;
            cp16(adst, &ALg[(size_t)arow * Ktot + k0 + acol]);
        }
        CP_COMMIT();
    };

    issue(0);
    if (nch > 1) issue(1);

    for (int c = 0; c < nch; ++c) {
        if (c + 1 < nch) CP_WAIT1(); else CP_WAIT0();
        __syncthreads();
        if (c + 2 < nch) issue(c + 2);

        int slot = c % STAGES;
        const float* Ws = (const float*)(sm + slot * WS_BYTES);
        uint32_t ah_base = smem_u32(sm + SM_AH_OFF + slot * AH_BYTES) + ((lane & 15) * A_STRIDE + (lane >> 4) * 8) * 2;
        uint32_t al_base = smem_u32(sm + SM_AL_OFF + slot * AH_BYTES) + ((lane & 15) * A_STRIDE + (lane >> 4) * 8) * 2;

        #pragma unroll
        for (int ks2 = 0; ks2 < 2; ++ks2) {
            uint32_t ah0[4], ah1[4], al0[4], al1[4];
            ldsm4(ah0[0], ah0[1], ah0[2], ah0[3], ah_base + ks2 * 32);
            ldsm4(ah1[0], ah1[1], ah1[2], ah1[3], ah_base + ks2 * 32 + 16 * A_STRIDE * 2);
            ldsm4(al0[0], al0[1], al0[2], al0[3], al_base + ks2 * 32);
            ldsm4(al1[0], al1[1], al1[2], al1[3], al_base + ks2 * 32 + 16 * A_STRIDE * 2);
            #pragma unroll
            for (int nf = 0; nf < 2; ++nf) {
                int cc = n0 + nf * 8 + (lane >> 2);
                int kk = ks2 * 16 + (lane & 3) * 2;
                const float* wp = &Ws[kk * W_STRIDE + cc];
                float f0 = wp[0];
                float f1 = wp[W_STRIDE];
                float f2 = wp[8 * W_STRIDE];
                float f3 = wp[9 * W_STRIDE];
                uint32_t b0h, b0l, b1h, b1l;
                split2(f0, f1, b0h, b0l);
                split2(f2, f3, b1h, b1l);
                mma16816(acc[0][nf], ah0[0], ah0[1], ah0[2], ah0[3], b0h, b1h);
                mma16816(acc[1][nf], ah1[0], ah1[1], ah1[2], ah1[3], b0h, b1h);
                mma16816(acc[0][nf], al0[0], al0[1], al0[2], al0[3], b0h, b1h);
                mma16816(acc[1][nf], al1[0], al1[1], al1[2], al1[3], b0h, b1h);
                mma16816(acc[0][nf], ah0[0], ah0[1], ah0[2], ah0[3], b0l, b1l);
                mma16816(acc[1][nf], ah1[0], ah1[1], ah1[2], ah1[3], b0l, b1l);
            }
        }
    }

    #pragma unroll
    for (int mt = 0; mt < 2; ++mt) {
        int r = mt * 16 + (lane >> 2);
        #pragma unroll
        for (int nf = 0; nf < 2; ++nf) {
            int nc = n0 + nf * 8 + (lane & 3) * 2;
            *(float2*)&P[(size_t)r * OO + nc]       = make_float2(acc[mt][nf][0], acc[mt][nf][1]);
            *(float2*)&P[(size_t)(r + 8) * OO + nc] = make_float2(acc[mt][nf][2], acc[mt][nf][3]);
        }
    }
}

// ---------------- 4) split-K reduce ----------------
template<int MODE>
__global__ void reduce_kernel(const float* __restrict__ bias, float* __restrict__ outF) {
    int i = blockIdx.x * 256 + threadIdx.x;
    int n4 = i & (OO / 4 - 1);
    int m  = (i >> 8) & (BB - 1);
    int e  = i >> 13;

    float4 a = ((const float4*)&g_part[((size_t)e * BB + m) * OO])[n4];
    #pragma unroll
    for (int s = 1; s < SPLIT; ++s) {
        float4 v = ((const float4*)&g_part[((size_t)(s * EE + e) * BB + m) * OO])[n4];
        a.x += v.x; a.y += v.y; a.z += v.z; a.w += v.w;
    }
    float4 bb = ((const float4*)&bias[(size_t)e * OO])[n4];
    a.x += bb.x; a.y += bb.y; a.z += bb.z; a.w += bb.w;
    if (MODE < 2) {
        a.x = fmaxf(a.x, 0.f); a.y = fmaxf(a.y, 0.f);
        a.z = fmaxf(a.z, 0.f); a.w = fmaxf(a.w, 0.f);
        __nv_bfloat16* dh = (MODE == 0) ? g_h1h : g_h2h;
        __nv_bfloat16* dl = (MODE == 0) ? g_h1l : g_h2l;
        size_t off = ((size_t)(e * BB + m)) * OO + n4 * 4;
        uint32_t h0, l0, h1, l1;
        split2(a.x, a.y, h0, l0);
        split2(a.z, a.w, h1, l1);
        *(uint2*)&dh[off] = make_uint2(h0, h1);
        *(uint2*)&dl[off] = make_uint2(l0, l1);
    } else {
        ((float4*)&outF[((size_t)m * EE + e) * OO])[n4] = a;
    }
}

// ---------------- launch ----------------
extern "C" void kernel_launch(void* const* d_in, const int* in_sizes, int n_in,
                              void* d_out, int out_size) {
    const float* x  = (const float*)d_in[0];
    const float* Wg = (const float*)d_in[1];
    const float* bg = (const float*)d_in[2];
    const float* W1 = (const float*)d_in[3];
    const float* b1 = (const float*)d_in[4];
    const float* W2 = (const float*)d_in[5];
    const float* b2 = (const float*)d_in[6];
    const float* W3 = (const float*)d_in[7];
    const float* b3 = (const float*)d_in[8];
    float* out = (float*)d_out;

    static bool attr_done = false;
    if (!attr_done) {
        cudaFuncSetAttribute(gate_kernel, cudaFuncAttributeMaxDynamicSharedMemorySize, GATE_SM);
        cudaFuncSetAttribute(expert_mma<0>, cudaFuncAttributeMaxDynamicSharedMemorySize, SM_TOTAL);
        cudaFuncSetAttribute(expert_mma<1>, cudaFuncAttributeMaxDynamicSharedMemorySize, SM_TOTAL);
        cudaFuncSetAttribute(expert_mma<2>, cudaFuncAttributeMaxDynamicSharedMemorySize, SM_TOTAL);
        attr_done = true;
    }

    const int RED_GRID = (EE * BB * OO / 4) / 256;   // 512

    wg_transpose<<<EE, 256>>>(Wg);
    gate_kernel<<<(BB * SS) / 128, 256, GATE_SM>>>(x, bg);
    topk_gather_kernel<<<dim3(EE, BB), 256>>>(x);

    expert_mma<0><<<dim3(OO / 128, EE, SPLIT), 256, SM_TOTAL>>>(W1, KD);
    reduce_kernel<0><<<RED_GRID, 256>>>(b1, nullptr);

    expert_mma<1><<<dim3(OO / 128, EE, SPLIT), 256, SM_TOTAL>>>(W2, OO);
    reduce_kernel<1><<<RED_GRID, 256>>>(b2, nullptr);

    expert_mma<2><<<dim3(OO / 128, EE, SPLIT), 256, SM_TOTAL>>>(W3, OO);
    reduce_kernel<2><<<RED_GRID, 256>>>(b3, out);
}

// round 8
// speedup vs baseline: 1.0875x; 1.0875x over previous
#include <cuda_runtime.h>
#include <cuda_bf16.h>
#include <float.h>
#include <cstdint>

// Problem constants
#define BB 32
#define SS 2048
#define DD 1024
#define EE 16
#define KK 4
#define OO 1024
#define KD 4096   // KK*DD
#define SPLIT 4

typedef unsigned long long ULL;

// ---------------- scratch (device globals) ----------------
__device__ float g_logits[BB * EE * SS];            // [B][E][S], 4 MB
__device__ __nv_bfloat16 g_inph[EE * BB * KD];      // inp hi, [e][b][4096]
__device__ __nv_bfloat16 g_inpl[EE * BB * KD];      // inp lo
__device__ __nv_bfloat16 g_h1h[EE * BB * OO];
__device__ __nv_bfloat16 g_h1l[EE * BB * OO];
__device__ __nv_bfloat16 g_h2h[EE * BB * OO];
__device__ __nv_bfloat16 g_h2l[EE * BB * OO];
__device__ float g_part[SPLIT * EE * BB * OO];      // split-K partials, 8 MB

// ---------------- f32x2 helpers (gate kernel) ----------------
__device__ __forceinline__ void fma2(ULL& d, ULL a, ULL b) {
    asm("fma.rn.f32x2 %0, %1, %2, %0;" : "+l"(d) : "l"(a), "l"(b));
}
__device__ __forceinline__ ULL dup2(float w) {
    ULL r; asm("mov.b64 %0, {%1, %1};" : "=l"(r) : "f"(w)); return r;
}
__device__ __forceinline__ float2 unpack2(ULL v) {
    float2 f; asm("mov.b64 {%0, %1}, %2;" : "=f"(f.x), "=f"(f.y) : "l"(v)); return f;
}

// ---------------- bf16 split helper ----------------
__device__ __forceinline__ void split2(float a, float b, uint32_t& hi, uint32_t& lo) {
    asm("cvt.rn.satfinite.bf16x2.f32 %0, %1, %2;" : "=r"(hi) : "f"(b), "f"(a));
    __nv_bfloat162 hp = *reinterpret_cast<__nv_bfloat162*>(&hi);
    float r0 = a - __low2float(hp);
    float r1 = b - __high2float(hp);
    asm("cvt.rn.satfinite.bf16x2.f32 %0, %1, %2;" : "=r"(lo) : "f"(r1), "f"(r0));
}

// ---------------- portable tensor-core / async helpers ----------------
__device__ __forceinline__ uint32_t smem_u32(const void* p) {
    uint32_t a;
    asm("{ .reg .u64 t; cvta.to.shared.u64 t, %1; cvt.u32.u64 %0, t; }" : "=r"(a) : "l"(p));
    return a;
}
__device__ __forceinline__ void ldsm4(uint32_t& r0, uint32_t& r1, uint32_t& r2, uint32_t& r3, uint32_t addr) {
    asm volatile("ldmatrix.sync.aligned.m8n8.x4.shared.b16 {%0,%1,%2,%3}, [%4];"
        : "=r"(r0), "=r"(r1), "=r"(r2), "=r"(r3) : "r"(addr));
}
__device__ __forceinline__ void mma16816(float* c, uint32_t a0, uint32_t a1, uint32_t a2, uint32_t a3,
                                         uint32_t b0, uint32_t b1) {
    asm("mma.sync.aligned.m16n8k16.row.col.f32.bf16.bf16.f32 "
        "{%0,%1,%2,%3}, {%4,%5,%6,%7}, {%8,%9}, {%0,%1,%2,%3};"
        : "+f"(c[0]), "+f"(c[1]), "+f"(c[2]), "+f"(c[3])
        : "r"(a0), "r"(a1), "r"(a2), "r"(a3), "r"(b0), "r"(b1));
}
__device__ __forceinline__ void cp16(uint32_t smem_dst, const void* gsrc) {
    asm volatile("cp.async.cg.shared.global [%0], [%1], 16;" :: "r"(smem_dst), "l"(gsrc));
}
#define CP_COMMIT() asm volatile("cp.async.commit_group;" ::: "memory")
#define CP_WAIT0()  asm volatile("cp.async.wait_group 0;" ::: "memory")

// ---------------- 1) gate GEMM (R6 version: 128 thr, reg-prefetch f32x2) ----
__global__ void gate_kernel(const float* __restrict__ x,
                            const float* __restrict__ Wg,
                            const float* __restrict__ bg) {
    __shared__ __align__(16) float As[2][32][132];
    __shared__ __align__(16) float Wgs[2][32][16];

    int tid = threadIdx.x;
    int t0 = blockIdx.x * 128;
    int b  = t0 >> 11;
    int s0 = t0 & 2047;

    int kq = (tid & 7) * 4;
    int am = tid >> 3;
    int kk = tid >> 2;
    int e4 = (tid & 3) * 4;
    int tx = tid & 7;
    int ty = tid >> 3;
    int e0 = tx * 2;
    int m0 = ty * 8;

    ULL acc[4][2];
    #pragma unroll
    for (int p = 0; p < 4; ++p) { acc[p][0] = 0ULL; acc[p][1] = 0ULL; }

    const int nch = DD / 32;
    float4 ra[8];
    float4 rwg;

    #pragma unroll
    for (int p = 0; p < 8; ++p)
        ra[p] = *(const float4*)&x[(size_t)(t0 + am + 16 * p) * DD + kq];
    rwg = *(const float4*)&Wg[(size_t)kk * EE + e4];

    #pragma unroll
    for (int p = 0; p < 8; ++p) {
        int m = am + 16 * p;
        As[0][kq + 0][m] = ra[p].x; As[0][kq + 1][m] = ra[p].y;
        As[0][kq + 2][m] = ra[p].z; As[0][kq + 3][m] = ra[p].w;
    }
    *(float4*)&Wgs[0][kk][e4] = rwg;
    __syncthreads();

    for (int c = 0; c < nch; ++c) {
        int cur = c & 1;
        if (c + 1 < nch) {
            int kc = (c + 1) * 32;
            #pragma unroll
            for (int p = 0; p < 8; ++p)
                ra[p] = *(const float4*)&x[(size_t)(t0 + am + 16 * p) * DD + kc + kq];
            rwg = *(const float4*)&Wg[(size_t)(kc + kk) * EE + e4];
        }
        #pragma unroll
        for (int k = 0; k < 32; ++k) {
            ulonglong2 a01 = *(const ulonglong2*)&As[cur][k][m0];
            ulonglong2 a23 = *(const ulonglong2*)&As[cur][k][m0 + 4];
            float2 wv = *(const float2*)&Wgs[cur][k][e0];
            ULL w0 = dup2(wv.x), w1 = dup2(wv.y);
            fma2(acc[0][0], a01.x, w0); fma2(acc[1][0], a01.y, w0);
            fma2(acc[2][0], a23.x, w0); fma2(acc[3][0], a23.y, w0);
            fma2(acc[0][1], a01.x, w1); fma2(acc[1][1], a01.y, w1);
            fma2(acc[2][1], a23.x, w1); fma2(acc[3][1], a23.y, w1);
        }
        if (c + 1 < nch) {
            int nb = (c + 1) & 1;
            #pragma unroll
            for (int p = 0; p < 8; ++p) {
                int m = am + 16 * p;
                As[nb][kq + 0][m] = ra[p].x; As[nb][kq + 1][m] = ra[p].y;
                As[nb][kq + 2][m] = ra[p].z; As[nb][kq + 3][m] = ra[p].w;
            }
            *(float4*)&Wgs[nb][kk][e4] = rwg;
            __syncthreads();
        }
    }

    #pragma unroll
    for (int j = 0; j < 2; ++j) {
        float bb = bg[e0 + j];
        float* dst = &g_logits[((size_t)(b * EE) + e0 + j) * SS];
        #pragma unroll
        for (int p = 0; p < 4; ++p) {
            float2 v = unpack2(acc[p][j]);
            int s = s0 + m0 + 2 * p;
            *(float2*)&dst[s] = make_float2(v.x + bb, v.y + bb);
        }
    }
}

// ---------------- 2) softmax(+top4) + gather (bf16-split output) ----------------
__global__ void topk_gather_kernel(const float* __restrict__ x) {
    int e = blockIdx.x, b = blockIdx.y;
    __shared__ float sv[SS];
    __shared__ float red[256];
    __shared__ int   redi[256];
    __shared__ float s_max, s_sum;
    __shared__ int   s_idx[KK];
    __shared__ float s_val[KK];
    int tid = threadIdx.x;

    const float* row = &g_logits[(size_t)(b * EE + e) * SS];
    float lmax = -FLT_MAX;
    for (int i = tid; i < SS; i += 256) {
        float v = row[i];
        sv[i] = v;
        lmax = fmaxf(lmax, v);
    }
    red[tid] = lmax;
    __syncthreads();
    for (int off = 128; off > 0; off >>= 1) {
        if (tid < off) red[tid] = fmaxf(red[tid], red[tid + off]);
        __syncthreads();
    }
    if (tid == 0) s_max = red[0];
    __syncthreads();
    float mx = s_max;

    float lsum = 0.f;
    for (int i = tid; i < SS; i += 256) lsum += expf(sv[i] - mx);
    red[tid] = lsum;
    __syncthreads();
    for (int off = 128; off > 0; off >>= 1) {
        if (tid < off) red[tid] += red[tid + off];
        __syncthreads();
    }
    if (tid == 0) s_sum = red[0];
    __syncthreads();
    float inv = 1.0f / s_sum;

    for (int it = 0; it < KK; ++it) {
        float bv = -FLT_MAX;
        int bi = SS;
        for (int i = tid; i < SS; i += 256) {
            float v = sv[i];
            if (v > bv) { bv = v; bi = i; }
        }
        red[tid] = bv; redi[tid] = bi;
        __syncthreads();
        for (int off = 128; off > 0; off >>= 1) {
            if (tid < off) {
                float v2 = red[tid + off]; int i2 = redi[tid + off];
                if (v2 > red[tid] || (v2 == red[tid] && i2 < redi[tid])) {
                    red[tid] = v2; redi[tid] = i2;
                }
            }
            __syncthreads();
        }
        if (tid == 0) {
            int wi = redi[0];
            s_idx[it] = wi;
            s_val[it] = expf(red[0] - mx) * inv;
            sv[wi] = -FLT_MAX;
        }
        __syncthreads();
    }

    // gather, scale, bf16-split -> g_inph / g_inpl [e][b][j*D + d]
    #pragma unroll
    for (int j = 0; j < KK; ++j) {
        int idx = s_idx[j];
        float w = s_val[j];
        const float4* src = (const float4*)&x[((size_t)b * SS + idx) * DD];
        __nv_bfloat16* dh = &g_inph[((size_t)(e * BB + b)) * KD + j * DD];
        __nv_bfloat16* dl = &g_inpl[((size_t)(e * BB + b)) * KD + j * DD];
        int d4 = tid;
        float4 v = src[d4];
        v.x *= w; v.y *= w; v.z *= w; v.w *= w;
        uint32_t h0, l0, h1, l1;
        split2(v.x, v.y, h0, l0);
        split2(v.z, v.w, h1, l1);
        *(uint2*)&dh[d4 * 4] = make_uint2(h0, h1);
        *(uint2*)&dl[d4 * 4] = make_uint2(l0, l1);
    }
}

// ---------------- 3) expert GEMM: 2-stage cp.async, 4 CTAs/SM, single wave ----
#define STAGES 2
#define A_STRIDE 40                    // bf16 per A row (32 + 8 pad)
#define W_STRIDE 132                   // floats per W row (128 + 4 pad)
#define WS_BYTES (32 * W_STRIDE * 4)   // 16896 per stage
#define AH_BYTES (32 * A_STRIDE * 2)   // 2560 per stage
#define SM_AH_OFF (STAGES * WS_BYTES)
#define SM_AL_OFF (SM_AH_OFF + STAGES * AH_BYTES)
#define SM_TOTAL  (SM_AL_OFF + STAGES * AH_BYTES)   // 44032

template<int MODE>
__global__ void __launch_bounds__(256, 4) expert_mma(const float* __restrict__ W, int Ktot) {
    extern __shared__ __align__(16) uint8_t sm[];

    int e = blockIdx.y, nt = blockIdx.x, ks = blockIdx.z;
    const int Ksub = Ktot / SPLIT;
    const int k0base = ks * Ksub;
    const int nch = Ksub >> 5;

    const __nv_bfloat16 *srcH, *srcL;
    if (MODE == 0)      { srcH = g_inph; srcL = g_inpl; }
    else if (MODE == 1) { srcH = g_h1h;  srcL = g_h1l; }
    else                { srcH = g_h2h;  srcL = g_h2l; }
    const __nv_bfloat16* AHg = srcH + (size_t)e * BB * Ktot;
    const __nv_bfloat16* ALg = srcL + (size_t)e * BB * Ktot;
    const float* We = W + (size_t)e * Ktot * OO + nt * 128;
    float* P = g_part + ((size_t)(ks * EE + e) * BB) * OO + nt * 128;

    int tid = threadIdx.x, lane = tid & 31, wid = tid >> 5;
    int n0 = wid * 16;

    int wrow = tid >> 3;
    int wcol = (tid & 7) * 16;
    int arow = (tid & 127) >> 2;
    int acol = (tid & 3) * 8;

    float acc[2][2][4];
    #pragma unroll
    for (int mt = 0; mt < 2; ++mt)
        #pragma unroll
        for (int nf = 0; nf < 2; ++nf)
            #pragma unroll
            for (int q = 0; q < 4; ++q) acc[mt][nf][q] = 0.f;

    auto issue = [&](int c) {
        int slot = c & 1;
        int k0 = k0base + c * 32;
        uint32_t wdst = smem_u32(sm + slot * WS_BYTES) + (wrow * W_STRIDE + wcol) * 4;
        const float* wsrc = &We[(size_t)(k0 + wrow) * OO + wcol];
        #pragma unroll
        for (int i = 0; i < 4; ++i)
            cp16(wdst + i * 16, wsrc + i * 4);
        if (tid < 128) {
            uint32_t adst = smem_u32(sm + SM_AH_OFF + slot * AH_BYTES) + (arow * A_STRIDE + acol) * 2;
            cp16(adst, &AHg[(size_t)arow * Ktot + k0 + acol]);
        } else {
            uint32_t adst = smem_u32(sm + SM_AL_OFF + slot * AH_BYTES) + (arow * A_STRIDE + acol) * 2;
            cp16(adst, &ALg[(size_t)arow * Ktot + k0 + acol]);
        }
        CP_COMMIT();
    };

    issue(0);

    for (int c = 0; c < nch; ++c) {
        CP_WAIT0();            // chunk c staged (it was the last group issued)
        __syncthreads();       // also guarantees compute of c-1 finished CTA-wide
        if (c + 1 < nch) issue(c + 1);   // fill the other buffer while computing c

        int slot = c & 1;
        const float* Ws = (const float*)(sm + slot * WS_BYTES);
        uint32_t ah_base = smem_u32(sm + SM_AH_OFF + slot * AH_BYTES) + ((lane & 15) * A_STRIDE + (lane >> 4) * 8) * 2;
        uint32_t al_base = smem_u32(sm + SM_AL_OFF + slot * AH_BYTES) + ((lane & 15) * A_STRIDE + (lane >> 4) * 8) * 2;

        #pragma unroll
        for (int ks2 = 0; ks2 < 2; ++ks2) {
            uint32_t ah0[4], ah1[4], al0[4], al1[4];
            ldsm4(ah0[0], ah0[1], ah0[2], ah0[3], ah_base + ks2 * 32);
            ldsm4(ah1[0], ah1[1], ah1[2], ah1[3], ah_base + ks2 * 32 + 16 * A_STRIDE * 2);
            ldsm4(al0[0], al0[1], al0[2], al0[3], al_base + ks2 * 32);
            ldsm4(al1[0], al1[1], al1[2], al1[3], al_base + ks2 * 32 + 16 * A_STRIDE * 2);
            #pragma unroll
            for (int nf = 0; nf < 2; ++nf) {
                int cc = n0 + nf * 8 + (lane >> 2);
                int kk = ks2 * 16 + (lane & 3) * 2;
                const float* wp = &Ws[kk * W_STRIDE + cc];
                float f0 = wp[0];
                float f1 = wp[W_STRIDE];
                float f2 = wp[8 * W_STRIDE];
                float f3 = wp[9 * W_STRIDE];
                uint32_t b0h, b0l, b1h, b1l;
                split2(f0, f1, b0h, b0l);
                split2(f2, f3, b1h, b1l);
                mma16816(acc[0][nf], ah0[0], ah0[1], ah0[2], ah0[3], b0h, b1h);
                mma16816(acc[1][nf], ah1[0], ah1[1], ah1[2], ah1[3], b0h, b1h);
                mma16816(acc[0][nf], al0[0], al0[1], al0[2], al0[3], b0h, b1h);
                mma16816(acc[1][nf], al1[0], al1[1], al1[2], al1[3], b0h, b1h);
                mma16816(acc[0][nf], ah0[0], ah0[1], ah0[2], ah0[3], b0l, b1l);
                mma16816(acc[1][nf], ah1[0], ah1[1], ah1[2], ah1[3], b0l, b1l);
            }
        }
    }

    #pragma unroll
    for (int mt = 0; mt < 2; ++mt) {
        int r = mt * 16 + (lane >> 2);
        #pragma unroll
        for (int nf = 0; nf < 2; ++nf) {
            int nc = n0 + nf * 8 + (lane & 3) * 2;
            *(float2*)&P[(size_t)r * OO + nc]       = make_float2(acc[mt][nf][0], acc[mt][nf][1]);
            *(float2*)&P[(size_t)(r + 8) * OO + nc] = make_float2(acc[mt][nf][2], acc[mt][nf][3]);
        }
    }
}

// ---------------- 4) split-K reduce ----------------
template<int MODE>
__global__ void reduce_kernel(const float* __restrict__ bias, float* __restrict__ outF) {
    int i = blockIdx.x * 256 + threadIdx.x;
    int n4 = i & (OO / 4 - 1);
    int m  = (i >> 8) & (BB - 1);
    int e  = i >> 13;

    float4 a = ((const float4*)&g_part[((size_t)e * BB + m) * OO])[n4];
    #pragma unroll
    for (int s = 1; s < SPLIT; ++s) {
        float4 v = ((const float4*)&g_part[((size_t)(s * EE + e) * BB + m) * OO])[n4];
        a.x += v.x; a.y += v.y; a.z += v.z; a.w += v.w;
    }
    float4 bb = ((const float4*)&bias[(size_t)e * OO])[n4];
    a.x += bb.x; a.y += bb.y; a.z += bb.z; a.w += bb.w;
    if (MODE < 2) {
        a.x = fmaxf(a.x, 0.f); a.y = fmaxf(a.y, 0.f);
        a.z = fmaxf(a.z, 0.f); a.w = fmaxf(a.w, 0.f);
        __nv_bfloat16* dh = (MODE == 0) ? g_h1h : g_h2h;
        __nv_bfloat16* dl = (MODE == 0) ? g_h1l : g_h2l;
        size_t off = ((size_t)(e * BB + m)) * OO + n4 * 4;
        uint32_t h0, l0, h1, l1;
        split2(a.x, a.y, h0, l0);
        split2(a.z, a.w, h1, l1);
        *(uint2*)&dh[off] = make_uint2(h0, h1);
        *(uint2*)&dl[off] = make_uint2(l0, l1);
    } else {
        ((float4*)&outF[((size_t)m * EE + e) * OO])[n4] = a;
    }
}

// ---------------- launch ----------------
extern "C" void kernel_launch(void* const* d_in, const int* in_sizes, int n_in,
                              void* d_out, int out_size) {
    const float* x  = (const float*)d_in[0];
    const float* Wg = (const float*)d_in[1];
    const float* bg = (const float*)d_in[2];
    const float* W1 = (const float*)d_in[3];
    const float* b1 = (const float*)d_in[4];
    const float* W2 = (const float*)d_in[5];
    const float* b2 = (const float*)d_in[6];
    const float* W3 = (const float*)d_in[7];
    const float* b3 = (const float*)d_in[8];
    float* out = (float*)d_out;

    static bool attr_done = false;
    if (!attr_done) {
        cudaFuncSetAttribute(expert_mma<0>, cudaFuncAttributeMaxDynamicSharedMemorySize, SM_TOTAL);
        cudaFuncSetAttribute(expert_mma<1>, cudaFuncAttributeMaxDynamicSharedMemorySize, SM_TOTAL);
        cudaFuncSetAttribute(expert_mma<2>, cudaFuncAttributeMaxDynamicSharedMemorySize, SM_TOTAL);
        attr_done = true;
    }

    const int RED_GRID = (EE * BB * OO / 4) / 256;   // 512

    gate_kernel<<<(BB * SS) / 128, 128>>>(x, Wg, bg);
    topk_gather_kernel<<<dim3(EE, BB), 256>>>(x);

    expert_mma<0><<<dim3(OO / 128, EE, SPLIT), 256, SM_TOTAL>>>(W1, KD);
    reduce_kernel<0><<<RED_GRID, 256>>>(b1, nullptr);

    expert_mma<1><<<dim3(OO / 128, EE, SPLIT), 256, SM_TOTAL>>>(W2, OO);
    reduce_kernel<1><<<RED_GRID, 256>>>(b2, nullptr);

    expert_mma<2><<<dim3(OO / 128, EE, SPLIT), 256, SM_TOTAL>>>(W3, OO);
    reduce_kernel<2><<<RED_GRID, 256>>>(b3, out);
}

// round 9
// speedup vs baseline: 1.1929x; 1.0969x over previous
#include <cuda_runtime.h>
#include <cuda_bf16.h>
#include <float.h>
#include <cstdint>

// Problem constants
#define BB 32
#define SS 2048
#define DD 1024
#define EE 16
#define KK 4
#define OO 1024
#define KD 4096   // KK*DD
#define SPLIT 4

typedef unsigned long long ULL;

// ---------------- scratch (device globals) ----------------
__device__ float g_logits[BB * EE * SS];            // [B][E][S], 4 MB
__device__ float g_wgt[EE * DD];                    // Wg transposed [e][k], 64 KB
__device__ __nv_bfloat16 g_inph[EE * BB * KD];      // inp hi, [e][b][4096]
__device__ __nv_bfloat16 g_inpl[EE * BB * KD];      // inp lo
__device__ __nv_bfloat16 g_h1h[EE * BB * OO];
__device__ __nv_bfloat16 g_h1l[EE * BB * OO];
__device__ __nv_bfloat16 g_h2h[EE * BB * OO];
__device__ __nv_bfloat16 g_h2l[EE * BB * OO];
__device__ float g_part[SPLIT * EE * BB * OO];      // split-K partials, 8 MB

// ---------------- f32x2 helpers ----------------
__device__ __forceinline__ void fma2(ULL& d, ULL a, ULL b) {
    asm("fma.rn.f32x2 %0, %1, %2, %0;" : "+l"(d) : "l"(a), "l"(b));
}
__device__ __forceinline__ float2 unpack2(ULL v) {
    float2 f; asm("mov.b64 {%0, %1}, %2;" : "=f"(f.x), "=f"(f.y) : "l"(v)); return f;
}

// ---------------- bf16 split helper ----------------
__device__ __forceinline__ void split2(float a, float b, uint32_t& hi, uint32_t& lo) {
    asm("cvt.rn.satfinite.bf16x2.f32 %0, %1, %2;" : "=r"(hi) : "f"(b), "f"(a));
    __nv_bfloat162 hp = *reinterpret_cast<__nv_bfloat162*>(&hi);
    float r0 = a - __low2float(hp);
    float r1 = b - __high2float(hp);
    asm("cvt.rn.satfinite.bf16x2.f32 %0, %1, %2;" : "=r"(lo) : "f"(r1), "f"(r0));
}

// ---------------- portable tensor-core / TMA-bulk helpers ----------------
__device__ __forceinline__ uint32_t smem_u32(const void* p) {
    uint32_t a;
    asm("{ .reg .u64 t; cvta.to.shared.u64 t, %1; cvt.u32.u64 %0, t; }" : "=r"(a) : "l"(p));
    return a;
}
__device__ __forceinline__ void ldsm4(uint32_t& r0, uint32_t& r1, uint32_t& r2, uint32_t& r3, uint32_t addr) {
    asm volatile("ldmatrix.sync.aligned.m8n8.x4.shared.b16 {%0,%1,%2,%3}, [%4];"
        : "=r"(r0), "=r"(r1), "=r"(r2), "=r"(r3) : "r"(addr));
}
__device__ __forceinline__ void mma16816(float* c, uint32_t a0, uint32_t a1, uint32_t a2, uint32_t a3,
                                         uint32_t b0, uint32_t b1) {
    asm("mma.sync.aligned.m16n8k16.row.col.f32.bf16.bf16.f32 "
        "{%0,%1,%2,%3}, {%4,%5,%6,%7}, {%8,%9}, {%0,%1,%2,%3};"
        : "+f"(c[0]), "+f"(c[1]), "+f"(c[2]), "+f"(c[3])
        : "r"(a0), "r"(a1), "r"(a2), "r"(a3), "r"(b0), "r"(b1));
}
// TMA 1D bulk copy global->shared, completes on mbarrier (sm_90+ portable PTX)
__device__ __forceinline__ void bulk_g2s(uint32_t dst, const void* src, uint32_t bytes, uint32_t mbar) {
    asm volatile("cp.async.bulk.shared::cta.global.mbarrier::complete_tx::bytes [%0], [%1], %2, [%3];"
        :: "r"(dst), "l"(src), "r"(bytes), "r"(mbar) : "memory");
}
#define MBARRIER_INIT(mbar, cnt) \
    asm volatile("mbarrier.init.shared.b64 [%0], %1;" :: "r"((uint32_t)(mbar)), "r"((uint32_t)(cnt)) : "memory")
#define MBARRIER_EXPECT_TX(mbar, bytes) \
    asm volatile("mbarrier.arrive.expect_tx.shared.b64 _, [%0], %1;" :: "r"((uint32_t)(mbar)), "r"((uint32_t)(bytes)) : "memory")
#define MBARRIER_WAIT_PARITY(mbar, par) do { \
    uint32_t _m = (uint32_t)(mbar); uint32_t _p = (uint32_t)(par); \
    asm volatile("{\n\t.reg .pred P1;\n\tWAIT_LOOP_%=:\n\t" \
        "mbarrier.try_wait.parity.acquire.cta.shared::cta.b64 P1, [%0], %1, 0x989680;\n\t" \
        "@P1 bra.uni WAIT_DONE_%=;\n\tbra.uni WAIT_LOOP_%=;\n\tWAIT_DONE_%=:\n\t}" \
        :: "r"(_m), "r"(_p) : "memory"); \
} while (0)

// ---------------- 0) Wg transpose: g_wgt[e][k] = Wg[k][e] ----------------
__global__ void wg_transpose(const float* __restrict__ Wg) {
    int e = blockIdx.x;
    for (int k = threadIdx.x; k < DD; k += 256)
        g_wgt[e * DD + k] = Wg[(size_t)k * EE + e];
}

// ---------------- 1) gate GEMM: TMA-bulk 2-stage, f32x2 packed over K ------
// CTA: 128 tokens x 16 experts, 256 threads. logits[B,E,S] = (x @ Wg + bg)^T
#define XROW 36                          // floats per token row (32 + 4 pad)
#define XS_BYTES (128 * XROW * 4)        // 18432 per stage
#define WG_ROW 36
#define WGS_BYTES (EE * WG_ROW * 4)      // 2304 per stage
#define GATE_SM (2 * (XS_BYTES + WGS_BYTES))     // 41472
#define GATE_TX (128 * 128 + EE * 128)           // 18432 bytes per stage

__global__ void __launch_bounds__(256) gate_kernel(const float* __restrict__ x,
                                                   const float* __restrict__ bg) {
    extern __shared__ __align__(16) uint8_t gsm[];
    __shared__ __align__(8) ULL s_mbar[2];
    uint8_t* xs  = gsm;                       // [2][128][XROW] floats
    uint8_t* wgs = gsm + 2 * XS_BYTES;        // [2][EE][WG_ROW] floats

    int tid = threadIdx.x;
    int t0 = blockIdx.x * 128;
    int b  = t0 >> 11;
    int s0 = t0 & 2047;

    uint32_t mb[2] = { smem_u32(&s_mbar[0]), smem_u32(&s_mbar[1]) };

    // compute maps
    int tx = tid & 7;                     // e-group
    int ty = tid >> 3;                    // token-group 0..31
    int e0 = tx * 2;
    int m0 = ty * 4;

    if (tid == 0) { MBARRIER_INIT(mb[0], 1); MBARRIER_INIT(mb[1], 1); }
    __syncthreads();

    ULL acc2[4][2];
    #pragma unroll
    for (int i = 0; i < 4; ++i) { acc2[i][0] = 0ULL; acc2[i][1] = 0ULL; }

    const int nch = DD / 32;              // 32 chunks

    auto issue = [&](int c) {
        int slot = c & 1;
        int k0 = c * 32;
        if (tid == 0) MBARRIER_EXPECT_TX(mb[slot], GATE_TX);
        if (tid < 128) {
            // x row: 32 floats = 128B
            uint32_t dst = smem_u32(xs + slot * XS_BYTES) + tid * XROW * 4;
            bulk_g2s(dst, &x[(size_t)(t0 + tid) * DD + k0], 128, mb[slot]);
        } else if (tid < 128 + EE) {
            int e = tid - 128;
            uint32_t dst = smem_u32(wgs + slot * WGS_BYTES) + e * WG_ROW * 4;
            bulk_g2s(dst, &g_wgt[e * DD + k0], 128, mb[slot]);
        }
    };

    int ph[2] = {0, 0};
    issue(0);

    for (int c = 0; c < nch; ++c) {
        int slot = c & 1;
        MBARRIER_WAIT_PARITY(mb[slot], ph[slot]);
        ph[slot] ^= 1;
        __syncthreads();
        if (c + 1 < nch) issue(c + 1);

        const float* xv = (const float*)(xs + slot * XS_BYTES);
        const float* wv = (const float*)(wgs + slot * WGS_BYTES);

        #pragma unroll
        for (int k4 = 0; k4 < 8; ++k4) {
            ulonglong2 wp0 = *(const ulonglong2*)&wv[(e0 + 0) * WG_ROW + k4 * 4];
            ulonglong2 wp1 = *(const ulonglong2*)&wv[(e0 + 1) * WG_ROW + k4 * 4];
            #pragma unroll
            for (int i = 0; i < 4; ++i) {
                ulonglong2 xp = *(const ulonglong2*)&xv[(m0 + i) * XROW + k4 * 4];
                fma2(acc2[i][0], xp.x, wp0.x);
                fma2(acc2[i][0], xp.y, wp0.y);
                fma2(acc2[i][1], xp.x, wp1.x);
                fma2(acc2[i][1], xp.y, wp1.y);
            }
        }
    }

    // epilogue: horizontal add over k-pairs, + bg, float4 store along S
    #pragma unroll
    for (int j = 0; j < 2; ++j) {
        float bb = bg[e0 + j];
        float4 o;
        float2 v0 = unpack2(acc2[0][j]);
        float2 v1 = unpack2(acc2[1][j]);
        float2 v2 = unpack2(acc2[2][j]);
        float2 v3 = unpack2(acc2[3][j]);
        o.x = v0.x + v0.y + bb;
        o.y = v1.x + v1.y + bb;
        o.z = v2.x + v2.y + bb;
        o.w = v3.x + v3.y + bb;
        *(float4*)&g_logits[((size_t)(b * EE) + e0 + j) * SS + s0 + m0] = o;
    }
}

// ---------------- 2) softmax(+top4) + gather (bf16-split output) ----------------
__global__ void topk_gather_kernel(const float* __restrict__ x) {
    int e = blockIdx.x, b = blockIdx.y;
    __shared__ float sv[SS];
    __shared__ float red[256];
    __shared__ int   redi[256];
    __shared__ float s_max, s_sum;
    __shared__ int   s_idx[KK];
    __shared__ float s_val[KK];
    int tid = threadIdx.x;

    const float* row = &g_logits[(size_t)(b * EE + e) * SS];
    float lmax = -FLT_MAX;
    for (int i = tid; i < SS; i += 256) {
        float v = row[i];
        sv[i] = v;
        lmax = fmaxf(lmax, v);
    }
    red[tid] = lmax;
    __syncthreads();
    for (int off = 128; off > 0; off >>= 1) {
        if (tid < off) red[tid] = fmaxf(red[tid], red[tid + off]);
        __syncthreads();
    }
    if (tid == 0) s_max = red[0];
    __syncthreads();
    float mx = s_max;

    float lsum = 0.f;
    for (int i = tid; i < SS; i += 256) lsum += expf(sv[i] - mx);
    red[tid] = lsum;
    __syncthreads();
    for (int off = 128; off > 0; off >>= 1) {
        if (tid < off) red[tid] += red[tid + off];
        __syncthreads();
    }
    if (tid == 0) s_sum = red[0];
    __syncthreads();
    float inv = 1.0f / s_sum;

    for (int it = 0; it < KK; ++it) {
        float bv = -FLT_MAX;
        int bi = SS;
        for (int i = tid; i < SS; i += 256) {
            float v = sv[i];
            if (v > bv) { bv = v; bi = i; }
        }
        red[tid] = bv; redi[tid] = bi;
        __syncthreads();
        for (int off = 128; off > 0; off >>= 1) {
            if (tid < off) {
                float v2 = red[tid + off]; int i2 = redi[tid + off];
                if (v2 > red[tid] || (v2 == red[tid] && i2 < redi[tid])) {
                    red[tid] = v2; redi[tid] = i2;
                }
            }
            __syncthreads();
        }
        if (tid == 0) {
            int wi = redi[0];
            s_idx[it] = wi;
            s_val[it] = expf(red[0] - mx) * inv;
            sv[wi] = -FLT_MAX;
        }
        __syncthreads();
    }

    // gather, scale, bf16-split -> g_inph / g_inpl [e][b][j*D + d]
    #pragma unroll
    for (int j = 0; j < KK; ++j) {
        int idx = s_idx[j];
        float w = s_val[j];
        const float4* src = (const float4*)&x[((size_t)b * SS + idx) * DD];
        __nv_bfloat16* dh = &g_inph[((size_t)(e * BB + b)) * KD + j * DD];
        __nv_bfloat16* dl = &g_inpl[((size_t)(e * BB + b)) * KD + j * DD];
        int d4 = tid;
        float4 v = src[d4];
        v.x *= w; v.y *= w; v.z *= w; v.w *= w;
        uint32_t h0, l0, h1, l1;
        split2(v.x, v.y, h0, l0);
        split2(v.z, v.w, h1, l1);
        *(uint2*)&dh[d4 * 4] = make_uint2(h0, h1);
        *(uint2*)&dl[d4 * 4] = make_uint2(l0, l1);
    }
}

// ---------------- 3) expert GEMM: TMA-bulk 2-stage + mma.sync bf16-split ----
#define A_STRIDE 40                    // bf16 per A row (32 + 8 pad)
#define W_STRIDE 132                   // floats per W row (128 + 4 pad)
#define WS_BYTES (32 * W_STRIDE * 4)   // 16896 per stage
#define AH_BYTES (32 * A_STRIDE * 2)   // 2560 per stage
#define SM_AH_OFF (2 * WS_BYTES)
#define SM_AL_OFF (SM_AH_OFF + 2 * AH_BYTES)
#define SM_TOTAL  (SM_AL_OFF + 2 * AH_BYTES)   // 44032
#define EXP_TX (32 * 512 + 32 * 64 + 32 * 64)  // 20480 bytes per stage

template<int MODE>
__global__ void __launch_bounds__(256) expert_mma(const float* __restrict__ W, int Ktot) {
    extern __shared__ __align__(16) uint8_t sm[];
    __shared__ __align__(8) ULL s_mbar[2];

    int e = blockIdx.y, nt = blockIdx.x, ks = blockIdx.z;
    const int Ksub = Ktot / SPLIT;
    const int k0base = ks * Ksub;
    const int nch = Ksub >> 5;

    const __nv_bfloat16 *srcH, *srcL;
    if (MODE == 0)      { srcH = g_inph; srcL = g_inpl; }
    else if (MODE == 1) { srcH = g_h1h;  srcL = g_h1l; }
    else                { srcH = g_h2h;  srcL = g_h2l; }
    const __nv_bfloat16* AHg = srcH + (size_t)e * BB * Ktot;
    const __nv_bfloat16* ALg = srcL + (size_t)e * BB * Ktot;
    const float* We = W + (size_t)e * Ktot * OO + nt * 128;
    float* P = g_part + ((size_t)(ks * EE + e) * BB) * OO + nt * 128;

    int tid = threadIdx.x, lane = tid & 31, wid = tid >> 5;
    int n0 = wid * 16;

    uint32_t mb[2] = { smem_u32(&s_mbar[0]), smem_u32(&s_mbar[1]) };
    if (tid == 0) { MBARRIER_INIT(mb[0], 1); MBARRIER_INIT(mb[1], 1); }
    __syncthreads();

    float acc[2][2][4];
    #pragma unroll
    for (int mt = 0; mt < 2; ++mt)
        #pragma unroll
        for (int nf = 0; nf < 2; ++nf)
            #pragma unroll
            for (int q = 0; q < 4; ++q) acc[mt][nf][q] = 0.f;

    auto issue = [&](int c) {
        int slot = c & 1;
        int k0 = k0base + c * 32;
        if (tid == 0) MBARRIER_EXPECT_TX(mb[slot], EXP_TX);
        if (tid < 32) {
            // W row: 128 floats = 512B
            uint32_t dst = smem_u32(sm + slot * WS_BYTES) + tid * W_STRIDE * 4;
            bulk_g2s(dst, &We[(size_t)(k0 + tid) * OO], 512, mb[slot]);
        } else if (tid < 64) {
            int r = tid - 32;   // A hi row: 32 bf16 = 64B
            uint32_t dst = smem_u32(sm + SM_AH_OFF + slot * AH_BYTES) + r * A_STRIDE * 2;
            bulk_g2s(dst, &AHg[(size_t)r * Ktot + k0], 64, mb[slot]);
        } else if (tid < 96) {
            int r = tid - 64;   // A lo row
            uint32_t dst = smem_u32(sm + SM_AL_OFF + slot * AH_BYTES) + r * A_STRIDE * 2;
            bulk_g2s(dst, &ALg[(size_t)r * Ktot + k0], 64, mb[slot]);
        }
    };

    int ph[2] = {0, 0};
    issue(0);

    for (int c = 0; c < nch; ++c) {
        int slot = c & 1;
        MBARRIER_WAIT_PARITY(mb[slot], ph[slot]);
        ph[slot] ^= 1;
        __syncthreads();
        if (c + 1 < nch) issue(c + 1);

        const float* Ws = (const float*)(sm + slot * WS_BYTES);
        uint32_t ah_base = smem_u32(sm + SM_AH_OFF + slot * AH_BYTES) + ((lane & 15) * A_STRIDE + (lane >> 4) * 8) * 2;
        uint32_t al_base = smem_u32(sm + SM_AL_OFF + slot * AH_BYTES) + ((lane & 15) * A_STRIDE + (lane >> 4) * 8) * 2;

        #pragma unroll
        for (int ks2 = 0; ks2 < 2; ++ks2) {
            uint32_t ah0[4], ah1[4], al0[4], al1[4];
            ldsm4(ah0[0], ah0[1], ah0[2], ah0[3], ah_base + ks2 * 32);
            ldsm4(ah1[0], ah1[1], ah1[2], ah1[3], ah_base + ks2 * 32 + 16 * A_STRIDE * 2);
            ldsm4(al0[0], al0[1], al0[2], al0[3], al_base + ks2 * 32);
            ldsm4(al1[0], al1[1], al1[2], al1[3], al_base + ks2 * 32 + 16 * A_STRIDE * 2);
            #pragma unroll
            for (int nf = 0; nf < 2; ++nf) {
                int cc = n0 + nf * 8 + (lane >> 2);
                int kk = ks2 * 16 + (lane & 3) * 2;
                const float* wp = &Ws[kk * W_STRIDE + cc];
                float f0 = wp[0];
                float f1 = wp[W_STRIDE];
                float f2 = wp[8 * W_STRIDE];
                float f3 = wp[9 * W_STRIDE];
                uint32_t b0h, b0l, b1h, b1l;
                split2(f0, f1, b0h, b0l);
                split2(f2, f3, b1h, b1l);
                mma16816(acc[0][nf], ah0[0], ah0[1], ah0[2], ah0[3], b0h, b1h);
                mma16816(acc[1][nf], ah1[0], ah1[1], ah1[2], ah1[3], b0h, b1h);
                mma16816(acc[0][nf], al0[0], al0[1], al0[2], al0[3], b0h, b1h);
                mma16816(acc[1][nf], al1[0], al1[1], al1[2], al1[3], b0h, b1h);
                mma16816(acc[0][nf], ah0[0], ah0[1], ah0[2], ah0[3], b0l, b1l);
                mma16816(acc[1][nf], ah1[0], ah1[1], ah1[2], ah1[3], b0l, b1l);
            }
        }
    }

    #pragma unroll
    for (int mt = 0; mt < 2; ++mt) {
        int r = mt * 16 + (lane >> 2);
        #pragma unroll
        for (int nf = 0; nf < 2; ++nf) {
            int nc = n0 + nf * 8 + (lane & 3) * 2;
            *(float2*)&P[(size_t)r * OO + nc]       = make_float2(acc[mt][nf][0], acc[mt][nf][1]);
            *(float2*)&P[(size_t)(r + 8) * OO + nc] = make_float2(acc[mt][nf][2], acc[mt][nf][3]);
        }
    }
}

// ---------------- 4) split-K reduce ----------------
template<int MODE>
__global__ void reduce_kernel(const float* __restrict__ bias, float* __restrict__ outF) {
    int i = blockIdx.x * 256 + threadIdx.x;
    int n4 = i & (OO / 4 - 1);
    int m  = (i >> 8) & (BB - 1);
    int e  = i >> 13;

    float4 a = ((const float4*)&g_part[((size_t)e * BB + m) * OO])[n4];
    #pragma unroll
    for (int s = 1; s < SPLIT; ++s) {
        float4 v = ((const float4*)&g_part[((size_t)(s * EE + e) * BB + m) * OO])[n4];
        a.x += v.x; a.y += v.y; a.z += v.z; a.w += v.w;
    }
    float4 bb = ((const float4*)&bias[(size_t)e * OO])[n4];
    a.x += bb.x; a.y += bb.y; a.z += bb.z; a.w += bb.w;
    if (MODE < 2) {
        a.x = fmaxf(a.x, 0.f); a.y = fmaxf(a.y, 0.f);
        a.z = fmaxf(a.z, 0.f); a.w = fmaxf(a.w, 0.f);
        __nv_bfloat16* dh = (MODE == 0) ? g_h1h : g_h2h;
        __nv_bfloat16* dl = (MODE == 0) ? g_h1l : g_h2l;
        size_t off = ((size_t)(e * BB + m)) * OO + n4 * 4;
        uint32_t h0, l0, h1, l1;
        split2(a.x, a.y, h0, l0);
        split2(a.z, a.w, h1, l1);
        *(uint2*)&dh[off] = make_uint2(h0, h1);
        *(uint2*)&dl[off] = make_uint2(l0, l1);
    } else {
        ((float4*)&outF[((size_t)m * EE + e) * OO])[n4] = a;
    }
}

// ---------------- launch ----------------
extern "C" void kernel_launch(void* const* d_in, const int* in_sizes, int n_in,
                              void* d_out, int out_size) {
    const float* x  = (const float*)d_in[0];
    const float* Wg = (const float*)d_in[1];
    const float* bg = (const float*)d_in[2];
    const float* W1 = (const float*)d_in[3];
    const float* b1 = (const float*)d_in[4];
    const float* W2 = (const float*)d_in[5];
    const float* b2 = (const float*)d_in[6];
    const float* W3 = (const float*)d_in[7];
    const float* b3 = (const float*)d_in[8];
    float* out = (float*)d_out;

    static bool attr_done = false;
    if (!attr_done) {
        cudaFuncSetAttribute(gate_kernel, cudaFuncAttributeMaxDynamicSharedMemorySize, GATE_SM);
        cudaFuncSetAttribute(expert_mma<0>, cudaFuncAttributeMaxDynamicSharedMemorySize, SM_TOTAL);
        cudaFuncSetAttribute(expert_mma<1>, cudaFuncAttributeMaxDynamicSharedMemorySize, SM_TOTAL);
        cudaFuncSetAttribute(expert_mma<2>, cudaFuncAttributeMaxDynamicSharedMemorySize, SM_TOTAL);
        attr_done = true;
    }

    const int RED_GRID = (EE * BB * OO / 4) / 256;   // 512

    wg_transpose<<<EE, 256>>>(Wg);
    gate_kernel<<<(BB * SS) / 128, 256, GATE_SM>>>(x, bg);
    topk_gather_kernel<<<dim3(EE, BB), 256>>>(x);

    expert_mma<0><<<dim3(OO / 128, EE, SPLIT), 256, SM_TOTAL>>>(W1, KD);
    reduce_kernel<0><<<RED_GRID, 256>>>(b1, nullptr);

    expert_mma<1><<<dim3(OO / 128, EE, SPLIT), 256, SM_TOTAL>>>(W2, OO);
    reduce_kernel<1><<<RED_GRID, 256>>>(b2, nullptr);

    expert_mma<2><<<dim3(OO / 128, EE, SPLIT), 256, SM_TOTAL>>>(W3, OO);
    reduce_kernel<2><<<RED_GRID, 256>>>(b3, out);
}

// round 11
// speedup vs baseline: 1.3715x; 1.1497x over previous
#include <cuda_runtime.h>
#include <cuda.h>
#include <cuda_bf16.h>
#include <float.h>
#include <cstdint>

// Problem constants
#define BB 32
#define SS 2048
#define DD 1024
#define EE 16
#define KK 4
#define OO 1024
#define KD 4096   // KK*DD
#define SPLIT 4

typedef unsigned long long ULL;

// ---------------- scratch (device globals) ----------------
__device__ float g_logits[BB * EE * SS];            // [B][E][S], 4 MB
__device__ float g_wgt[EE * DD];                    // Wg transposed [e][k], 64 KB
__device__ __nv_bfloat16 g_inph[EE * BB * KD];      // inp hi, [e][b][4096]
__device__ __nv_bfloat16 g_inpl[EE * BB * KD];      // inp lo
__device__ __nv_bfloat16 g_h1h[EE * BB * OO];
__device__ __nv_bfloat16 g_h1l[EE * BB * OO];
__device__ __nv_bfloat16 g_h2h[EE * BB * OO];
__device__ __nv_bfloat16 g_h2l[EE * BB * OO];
__device__ float g_part[SPLIT * EE * BB * OO];      // split-K partials, 8 MB

// ---------------- f32x2 helpers ----------------
__device__ __forceinline__ void fma2(ULL& d, ULL a, ULL b) {
    asm("fma.rn.f32x2 %0, %1, %2, %0;" : "+l"(d) : "l"(a), "l"(b));
}
__device__ __forceinline__ float2 unpack2(ULL v) {
    float2 f; asm("mov.b64 {%0, %1}, %2;" : "=f"(f.x), "=f"(f.y) : "l"(v)); return f;
}

// ---------------- bf16 split helper ----------------
__device__ __forceinline__ void split2(float a, float b, uint32_t& hi, uint32_t& lo) {
    asm("cvt.rn.satfinite.bf16x2.f32 %0, %1, %2;" : "=r"(hi) : "f"(b), "f"(a));
    __nv_bfloat162 hp = *reinterpret_cast<__nv_bfloat162*>(&hi);
    float r0 = a - __low2float(hp);
    float r1 = b - __high2float(hp);
    asm("cvt.rn.satfinite.bf16x2.f32 %0, %1, %2;" : "=r"(lo) : "f"(r1), "f"(r0));
}

// ---------------- portable tensor-core / TMA helpers ----------------
__device__ __forceinline__ uint32_t smem_u32(const void* p) {
    uint32_t a;
    asm("{ .reg .u64 t; cvta.to.shared.u64 t, %1; cvt.u32.u64 %0, t; }" : "=r"(a) : "l"(p));
    return a;
}
__device__ __forceinline__ void ldsm4(uint32_t& r0, uint32_t& r1, uint32_t& r2, uint32_t& r3, uint32_t addr) {
    asm volatile("ldmatrix.sync.aligned.m8n8.x4.shared.b16 {%0,%1,%2,%3}, [%4];"
        : "=r"(r0), "=r"(r1), "=r"(r2), "=r"(r3) : "r"(addr));
}
__device__ __forceinline__ void mma16816(float* c, uint32_t a0, uint32_t a1, uint32_t a2, uint32_t a3,
                                         uint32_t b0, uint32_t b1) {
    asm("mma.sync.aligned.m16n8k16.row.col.f32.bf16.bf16.f32 "
        "{%0,%1,%2,%3}, {%4,%5,%6,%7}, {%8,%9}, {%0,%1,%2,%3};"
        : "+f"(c[0]), "+f"(c[1]), "+f"(c[2]), "+f"(c[3])
        : "r"(a0), "r"(a1), "r"(a2), "r"(a3), "r"(b0), "r"(b1));
}
__device__ __forceinline__ void tma3d(uint32_t dst, const CUtensorMap* map,
                                      int c0, int c1, int c2, uint32_t mbar) {
    asm volatile("cp.async.bulk.tensor.3d.shared::cta.global.tile.mbarrier::complete_tx::bytes "
        "[%0], [%1, {%2, %3, %4}], [%5];"
        :: "r"(dst), "l"(map), "r"(c0), "r"(c1), "r"(c2), "r"(mbar) : "memory");
}
#define MBARRIER_INIT(mbar, cnt) \
    asm volatile("mbarrier.init.shared.b64 [%0], %1;" :: "r"((uint32_t)(mbar)), "r"((uint32_t)(cnt)) : "memory")
#define MBARRIER_EXPECT_TX(mbar, bytes) \
    asm volatile("mbarrier.arrive.expect_tx.shared.b64 _, [%0], %1;" :: "r"((uint32_t)(mbar)), "r"((uint32_t)(bytes)) : "memory")
#define MBARRIER_WAIT_PARITY(mbar, par) do { \
    uint32_t _m = (uint32_t)(mbar); uint32_t _p = (uint32_t)(par); \
    asm volatile("{\n\t.reg .pred P1;\n\tWAIT_LOOP_%=:\n\t" \
        "mbarrier.try_wait.parity.acquire.cta.shared::cta.b64 P1, [%0], %1, 0x989680;\n\t" \
        "@P1 bra.uni WAIT_DONE_%=;\n\tbra.uni WAIT_LOOP_%=;\n\tWAIT_DONE_%=:\n\t}" \
        :: "r"(_m), "r"(_p) : "memory"); \
} while (0)

// ---------------- 0) Wg transpose: g_wgt[e][k] = Wg[k][e] ----------------
__global__ void wg_transpose(const float* __restrict__ Wg) {
    int e = blockIdx.x;
    for (int k = threadIdx.x; k < DD; k += 256)
        g_wgt[e * DD + k] = Wg[(size_t)k * EE + e];
}

// ---------------- 1) gate GEMM: tensor-map TMA (SW128), f32x2 over K ------
// x tile: box (32 floats, 128 tokens), 128B rows, SW128. Wg: box (32, 16).
#define XS_BYTES (128 * 128)             // 16384 per stage (128 rows x 128B)
#define WGS_BYTES (EE * 128)             // 2048 per stage
#define GATE_SM (2 * (XS_BYTES + WGS_BYTES))     // 36864
#define GATE_TX (XS_BYTES + WGS_BYTES)           // 18432 per stage

__global__ void __launch_bounds__(256) gate_kernel(
        const __grid_constant__ CUtensorMap xmap,
        const __grid_constant__ CUtensorMap wgmap,
        const float* __restrict__ bg) {
    extern __shared__ __align__(1024) uint8_t gsm[];
    __shared__ __align__(8) ULL s_mbar[2];
    uint8_t* xs  = gsm;                       // [2][128 rows][128B], swizzled
    uint8_t* wgs = gsm + 2 * XS_BYTES;        // [2][16 rows][128B], swizzled

    int tid = threadIdx.x;
    int t0 = blockIdx.x * 128;
    int b  = t0 >> 11;
    int s0 = t0 & 2047;

    uint32_t mb[2] = { smem_u32(&s_mbar[0]), smem_u32(&s_mbar[1]) };

    int tx = tid & 7;
    int ty = tid >> 3;
    int e0 = tx * 2;
    int m0 = ty * 4;

    if (tid == 0) { MBARRIER_INIT(mb[0], 1); MBARRIER_INIT(mb[1], 1); }
    __syncthreads();

    ULL acc2[4][2];
    #pragma unroll
    for (int i = 0; i < 4; ++i) { acc2[i][0] = 0ULL; acc2[i][1] = 0ULL; }

    const int nch = DD / 32;

    auto issue = [&](int c) {
        int slot = c & 1;
        int k0 = c * 32;
        if (tid == 0) {
            MBARRIER_EXPECT_TX(mb[slot], GATE_TX);
            tma3d(smem_u32(xs + slot * XS_BYTES), &xmap, k0, s0, b, mb[slot]);
            tma3d(smem_u32(wgs + slot * WGS_BYTES), &wgmap, k0, 0, 0, mb[slot]);
        }
    };

    int ph[2] = {0, 0};
    issue(0);

    for (int c = 0; c < nch; ++c) {
        int slot = c & 1;
        MBARRIER_WAIT_PARITY(mb[slot], ph[slot]);
        ph[slot] ^= 1;
        __syncthreads();
        if (c + 1 < nch) issue(c + 1);

        const uint8_t* xv = xs + slot * XS_BYTES;
        const uint8_t* wv = wgs + slot * WGS_BYTES;

        #pragma unroll
        for (int k4 = 0; k4 < 8; ++k4) {
            // SW128 with 128B rows: 16B chunk index XORed with (row & 7)
            ulonglong2 wp0 = *(const ulonglong2*)(wv + (e0 + 0) * 128 + ((k4 * 16) ^ (((e0 + 0) & 7) << 4)));
            ulonglong2 wp1 = *(const ulonglong2*)(wv + (e0 + 1) * 128 + ((k4 * 16) ^ (((e0 + 1) & 7) << 4)));
            #pragma unroll
            for (int i = 0; i < 4; ++i) {
                int r = m0 + i;
                ulonglong2 xp = *(const ulonglong2*)(xv + r * 128 + ((k4 * 16) ^ ((r & 7) << 4)));
                fma2(acc2[i][0], xp.x, wp0.x);
                fma2(acc2[i][0], xp.y, wp0.y);
                fma2(acc2[i][1], xp.x, wp1.x);
                fma2(acc2[i][1], xp.y, wp1.y);
            }
        }
    }

    #pragma unroll
    for (int j = 0; j < 2; ++j) {
        float bb = bg[e0 + j];
        float4 o;
        float2 v0 = unpack2(acc2[0][j]);
        float2 v1 = unpack2(acc2[1][j]);
        float2 v2 = unpack2(acc2[2][j]);
        float2 v3 = unpack2(acc2[3][j]);
        o.x = v0.x + v0.y + bb;
        o.y = v1.x + v1.y + bb;
        o.z = v2.x + v2.y + bb;
        o.w = v3.x + v3.y + bb;
        *(float4*)&g_logits[((size_t)(b * EE) + e0 + j) * SS + s0 + m0] = o;
    }
}

// ---------------- 2) softmax(+top4) + gather (bf16-split output) ----------------
__global__ void topk_gather_kernel(const float* __restrict__ x) {
    int e = blockIdx.x, b = blockIdx.y;
    __shared__ float sv[SS];
    __shared__ float red[256];
    __shared__ int   redi[256];
    __shared__ float s_max, s_sum;
    __shared__ int   s_idx[KK];
    __shared__ float s_val[KK];
    int tid = threadIdx.x;

    const float* row = &g_logits[(size_t)(b * EE + e) * SS];
    float lmax = -FLT_MAX;
    for (int i = tid; i < SS; i += 256) {
        float v = row[i];
        sv[i] = v;
        lmax = fmaxf(lmax, v);
    }
    red[tid] = lmax;
    __syncthreads();
    for (int off = 128; off > 0; off >>= 1) {
        if (tid < off) red[tid] = fmaxf(red[tid], red[tid + off]);
        __syncthreads();
    }
    if (tid == 0) s_max = red[0];
    __syncthreads();
    float mx = s_max;

    float lsum = 0.f;
    for (int i = tid; i < SS; i += 256) lsum += expf(sv[i] - mx);
    red[tid] = lsum;
    __syncthreads();
    for (int off = 128; off > 0; off >>= 1) {
        if (tid < off) red[tid] += red[tid + off];
        __syncthreads();
    }
    if (tid == 0) s_sum = red[0];
    __syncthreads();
    float inv = 1.0f / s_sum;

    for (int it = 0; it < KK; ++it) {
        float bv = -FLT_MAX;
        int bi = SS;
        for (int i = tid; i < SS; i += 256) {
            float v = sv[i];
            if (v > bv) { bv = v; bi = i; }
        }
        red[tid] = bv; redi[tid] = bi;
        __syncthreads();
        for (int off = 128; off > 0; off >>= 1) {
            if (tid < off) {
                float v2 = red[tid + off]; int i2 = redi[tid + off];
                if (v2 > red[tid] || (v2 == red[tid] && i2 < redi[tid])) {
                    red[tid] = v2; redi[tid] = i2;
                }
            }
            __syncthreads();
        }
        if (tid == 0) {
            int wi = redi[0];
            s_idx[it] = wi;
            s_val[it] = expf(red[0] - mx) * inv;
            sv[wi] = -FLT_MAX;
        }
        __syncthreads();
    }

    #pragma unroll
    for (int j = 0; j < KK; ++j) {
        int idx = s_idx[j];
        float w = s_val[j];
        const float4* src = (const float4*)&x[((size_t)b * SS + idx) * DD];
        __nv_bfloat16* dh = &g_inph[((size_t)(e * BB + b)) * KD + j * DD];
        __nv_bfloat16* dl = &g_inpl[((size_t)(e * BB + b)) * KD + j * DD];
        int d4 = tid;
        float4 v = src[d4];
        v.x *= w; v.y *= w; v.z *= w; v.w *= w;
        uint32_t h0, l0, h1, l1;
        split2(v.x, v.y, h0, l0);
        split2(v.z, v.w, h1, l1);
        *(uint2*)&dh[d4 * 4] = make_uint2(h0, h1);
        *(uint2*)&dl[d4 * 4] = make_uint2(l0, l1);
    }
}

// ---------------- 3) expert GEMM: tensor-map TMA (W SW128 subtiles) ----------
// W: 4 subtiles of box (32 floats, 32 k-rows), 128B rows, SW128.
// A: box (40 bf16, 32 rows), pitch 80B, no swizzle (unchanged ldsm path).
#define A_STRIDE 40
#define W_SUB 4096                     // 32 rows * 128B per subtile
#define WS_BYTES (4 * W_SUB)           // 16384 per stage
#define AH_BYTES (32 * A_STRIDE * 2)   // 2560 per stage
#define SM_AH_OFF (2 * WS_BYTES)                  // 32768
#define SM_AL_OFF (SM_AH_OFF + 2 * AH_BYTES)      // 37888
#define SM_TOTAL  (SM_AL_OFF + 2 * AH_BYTES)      // 43008
#define EXP_TX (WS_BYTES + 2 * AH_BYTES)          // 21504 per stage

template<int MODE>
__global__ void __launch_bounds__(256) expert_mma(
        const __grid_constant__ CUtensorMap wmap,
        const __grid_constant__ CUtensorMap ahmap,
        const __grid_constant__ CUtensorMap almap,
        int Ktot) {
    extern __shared__ __align__(1024) uint8_t sm[];
    __shared__ __align__(8) ULL s_mbar[2];

    int e = blockIdx.y, nt = blockIdx.x, ks = blockIdx.z;
    const int Ksub = Ktot / SPLIT;
    const int k0base = ks * Ksub;
    const int nch = Ksub >> 5;

    float* P = g_part + ((size_t)(ks * EE + e) * BB) * OO + nt * 128;

    int tid = threadIdx.x, lane = tid & 31, wid = tid >> 5;
    int n0 = wid * 16;

    uint32_t mb[2] = { smem_u32(&s_mbar[0]), smem_u32(&s_mbar[1]) };
    if (tid == 0) { MBARRIER_INIT(mb[0], 1); MBARRIER_INIT(mb[1], 1); }
    __syncthreads();

    float acc[2][2][4];
    #pragma unroll
    for (int mt = 0; mt < 2; ++mt)
        #pragma unroll
        for (int nf = 0; nf < 2; ++nf)
            #pragma unroll
            for (int q = 0; q < 4; ++q) acc[mt][nf][q] = 0.f;

    auto issue = [&](int c) {
        int slot = c & 1;
        int k0 = k0base + c * 32;
        if (tid == 0) {
            MBARRIER_EXPECT_TX(mb[slot], EXP_TX);
            #pragma unroll
            for (int q = 0; q < 4; ++q)
                tma3d(smem_u32(sm + slot * WS_BYTES + q * W_SUB), &wmap,
                      nt * 128 + q * 32, k0, e, mb[slot]);
            tma3d(smem_u32(sm + SM_AH_OFF + slot * AH_BYTES), &ahmap, k0, 0, e, mb[slot]);
            tma3d(smem_u32(sm + SM_AL_OFF + slot * AH_BYTES), &almap, k0, 0, e, mb[slot]);
        }
    };

    int ph[2] = {0, 0};
    issue(0);

    for (int c = 0; c < nch; ++c) {
        int slot = c & 1;
        MBARRIER_WAIT_PARITY(mb[slot], ph[slot]);
        ph[slot] ^= 1;
        __syncthreads();
        if (c + 1 < nch) issue(c + 1);

        const uint8_t* Wb = sm + slot * WS_BYTES;
        uint32_t ah_base = smem_u32(sm + SM_AH_OFF + slot * AH_BYTES) + ((lane & 15) * A_STRIDE + (lane >> 4) * 8) * 2;
        uint32_t al_base = smem_u32(sm + SM_AL_OFF + slot * AH_BYTES) + ((lane & 15) * A_STRIDE + (lane >> 4) * 8) * 2;

        #pragma unroll
        for (int ks2 = 0; ks2 < 2; ++ks2) {
            uint32_t ah0[4], ah1[4], al0[4], al1[4];
            ldsm4(ah0[0], ah0[1], ah0[2], ah0[3], ah_base + ks2 * 32);
            ldsm4(ah1[0], ah1[1], ah1[2], ah1[3], ah_base + ks2 * 32 + 16 * A_STRIDE * 2);
            ldsm4(al0[0], al0[1], al0[2], al0[3], al_base + ks2 * 32);
            ldsm4(al1[0], al1[1], al1[2], al1[3], al_base + ks2 * 32 + 16 * A_STRIDE * 2);
            #pragma unroll
            for (int nf = 0; nf < 2; ++nf) {
                int cc = n0 + nf * 8 + (lane >> 2);
                int q = cc >> 5;
                int c4 = (cc & 31) * 4;
                int kk = ks2 * 16 + (lane & 3) * 2;
                const uint8_t* Wq = Wb + q * W_SUB;
                // SW128, 128B rows: 16B-chunk XOR (row & 7)
                float f0 = *(const float*)(Wq + (kk + 0) * 128 + (c4 ^ (((kk + 0) & 7) << 4)));
                float f1 = *(const float*)(Wq + (kk + 1) * 128 + (c4 ^ (((kk + 1) & 7) << 4)));
                float f2 = *(const float*)(Wq + (kk + 8) * 128 + (c4 ^ (((kk + 8) & 7) << 4)));
                float f3 = *(const float*)(Wq + (kk + 9) * 128 + (c4 ^ (((kk + 9) & 7) << 4)));
                uint32_t b0h, b0l, b1h, b1l;
                split2(f0, f1, b0h, b0l);
                split2(f2, f3, b1h, b1l);
                mma16816(acc[0][nf], ah0[0], ah0[1], ah0[2], ah0[3], b0h, b1h);
                mma16816(acc[1][nf], ah1[0], ah1[1], ah1[2], ah1[3], b0h, b1h);
                mma16816(acc[0][nf], al0[0], al0[1], al0[2], al0[3], b0h, b1h);
                mma16816(acc[1][nf], al1[0], al1[1], al1[2], al1[3], b0h, b1h);
                mma16816(acc[0][nf], ah0[0], ah0[1], ah0[2], ah0[3], b0l, b1l);
                mma16816(acc[1][nf], ah1[0], ah1[1], ah1[2], ah1[3], b0l, b1l);
            }
        }
    }

    #pragma unroll
    for (int mt = 0; mt < 2; ++mt) {
        int r = mt * 16 + (lane >> 2);
        #pragma unroll
        for (int nf = 0; nf < 2; ++nf) {
            int nc = n0 + nf * 8 + (lane & 3) * 2;
            *(float2*)&P[(size_t)r * OO + nc]       = make_float2(acc[mt][nf][0], acc[mt][nf][1]);
            *(float2*)&P[(size_t)(r + 8) * OO + nc] = make_float2(acc[mt][nf][2], acc[mt][nf][3]);
        }
    }
}

// ---------------- 4) split-K reduce ----------------
template<int MODE>
__global__ void reduce_kernel(const float* __restrict__ bias, float* __restrict__ outF) {
    int i = blockIdx.x * 256 + threadIdx.x;
    int n4 = i & (OO / 4 - 1);
    int m  = (i >> 8) & (BB - 1);
    int e  = i >> 13;

    float4 a = ((const float4*)&g_part[((size_t)e * BB + m) * OO])[n4];
    #pragma unroll
    for (int s = 1; s < SPLIT; ++s) {
        float4 v = ((const float4*)&g_part[((size_t)(s * EE + e) * BB + m) * OO])[n4];
        a.x += v.x; a.y += v.y; a.z += v.z; a.w += v.w;
    }
    float4 bb = ((const float4*)&bias[(size_t)e * OO])[n4];
    a.x += bb.x; a.y += bb.y; a.z += bb.z; a.w += bb.w;
    if (MODE < 2) {
        a.x = fmaxf(a.x, 0.f); a.y = fmaxf(a.y, 0.f);
        a.z = fmaxf(a.z, 0.f); a.w = fmaxf(a.w, 0.f);
        __nv_bfloat16* dh = (MODE == 0) ? g_h1h : g_h2h;
        __nv_bfloat16* dl = (MODE == 0) ? g_h1l : g_h2l;
        size_t off = ((size_t)(e * BB + m)) * OO + n4 * 4;
        uint32_t h0, l0, h1, l1;
        split2(a.x, a.y, h0, l0);
        split2(a.z, a.w, h1, l1);
        *(uint2*)&dh[off] = make_uint2(h0, h1);
        *(uint2*)&dl[off] = make_uint2(l0, l1);
    } else {
        ((float4*)&outF[((size_t)m * EE + e) * OO])[n4] = a;
    }
}

// ---------------- host: tensor map encoding via driver entry point ----------------
typedef CUresult (*PFN_tmEncode)(CUtensorMap*, CUtensorMapDataType, cuuint32_t, void*,
                                 const cuuint64_t*, const cuuint64_t*, const cuuint32_t*,
                                 const cuuint32_t*, CUtensorMapInterleave, CUtensorMapSwizzle,
                                 CUtensorMapL2promotion, CUtensorMapFloatOOBfill);

static void enc3(PFN_tmEncode enc, CUtensorMap* m, void* base, CUtensorMapDataType dt,
                 int elbytes, uint64_t d0, uint64_t d1, uint64_t d2,
                 uint32_t b0, uint32_t b1, CUtensorMapSwizzle sw) {
    cuuint64_t dims[3] = {d0, d1, d2};
    cuuint64_t strides[2] = {d0 * (uint64_t)elbytes, d0 * d1 * (uint64_t)elbytes};
    cuuint32_t box[3] = {b0, b1, 1};
    cuuint32_t es[3] = {1, 1, 1};
    enc(m, dt, 3, base, dims, strides, box, es,
        CU_TENSOR_MAP_INTERLEAVE_NONE, sw,
        CU_TENSOR_MAP_L2_PROMOTION_L2_128B, CU_TENSOR_MAP_FLOAT_OOB_FILL_NONE);
}

extern "C" void kernel_launch(void* const* d_in, const int* in_sizes, int n_in,
                              void* d_out, int out_size) {
    const float* x  = (const float*)d_in[0];
    const float* Wg = (const float*)d_in[1];
    const float* bg = (const float*)d_in[2];
    const float* W1 = (const float*)d_in[3];
    const float* b1 = (const float*)d_in[4];
    const float* W2 = (const float*)d_in[5];
    const float* b2 = (const float*)d_in[6];
    const float* W3 = (const float*)d_in[7];
    const float* b3 = (const float*)d_in[8];
    float* out = (float*)d_out;

    static bool attr_done = false;
    if (!attr_done) {
        cudaFuncSetAttribute(gate_kernel, cudaFuncAttributeMaxDynamicSharedMemorySize, GATE_SM);
        cudaFuncSetAttribute(expert_mma<0>, cudaFuncAttributeMaxDynamicSharedMemorySize, SM_TOTAL);
        cudaFuncSetAttribute(expert_mma<1>, cudaFuncAttributeMaxDynamicSharedMemorySize, SM_TOTAL);
        cudaFuncSetAttribute(expert_mma<2>, cudaFuncAttributeMaxDynamicSharedMemorySize, SM_TOTAL);
        attr_done = true;
    }

    PFN_tmEncode enc = nullptr;
    cudaDriverEntryPointQueryResult qr;
    cudaGetDriverEntryPoint("cuTensorMapEncodeTiled", (void**)&enc, cudaEnableDefault, &qr);

    void *p_wgt, *p_inph, *p_inpl, *p_h1h, *p_h1l, *p_h2h, *p_h2l;
    cudaGetSymbolAddress(&p_wgt, g_wgt);
    cudaGetSymbolAddress(&p_inph, g_inph);
    cudaGetSymbolAddress(&p_inpl, g_inpl);
    cudaGetSymbolAddress(&p_h1h, g_h1h);
    cudaGetSymbolAddress(&p_h1l, g_h1l);
    cudaGetSymbolAddress(&p_h2h, g_h2h);
    cudaGetSymbolAddress(&p_h2l, g_h2l);

    const CUtensorMapDataType F32 = CU_TENSOR_MAP_DATA_TYPE_FLOAT32;
    const CUtensorMapDataType BF16 = CU_TENSOR_MAP_DATA_TYPE_BFLOAT16;
    const CUtensorMapSwizzle SW128 = CU_TENSOR_MAP_SWIZZLE_128B;
    const CUtensorMapSwizzle SWN   = CU_TENSOR_MAP_SWIZZLE_NONE;

    CUtensorMap xmap, wgmap;
    enc3(enc, &xmap, (void*)x, F32, 4, DD, SS, BB, 32, 128, SW128);
    enc3(enc, &wgmap, p_wgt, F32, 4, DD, EE, 1, 32, EE, SW128);

    CUtensorMap w1m, w2m, w3m;
    enc3(enc, &w1m, (void*)W1, F32, 4, OO, KD, EE, 32, 32, SW128);
    enc3(enc, &w2m, (void*)W2, F32, 4, OO, OO, EE, 32, 32, SW128);
    enc3(enc, &w3m, (void*)W3, F32, 4, OO, OO, EE, 32, 32, SW128);

    CUtensorMap iph, ipl, h1h, h1l, h2h, h2l;
    enc3(enc, &iph, p_inph, BF16, 2, KD, BB, EE, A_STRIDE, 32, SWN);
    enc3(enc, &ipl, p_inpl, BF16, 2, KD, BB, EE, A_STRIDE, 32, SWN);
    enc3(enc, &h1h, p_h1h, BF16, 2, OO, BB, EE, A_STRIDE, 32, SWN);
    enc3(enc, &h1l, p_h1l, BF16, 2, OO, BB, EE, A_STRIDE, 32, SWN);
    enc3(enc, &h2h, p_h2h, BF16, 2, OO, BB, EE, A_STRIDE, 32, SWN);
    enc3(enc, &h2l, p_h2l, BF16, 2, OO, BB, EE, A_STRIDE, 32, SWN);

    const int RED_GRID = (EE * BB * OO / 4) / 256;   // 512

    wg_transpose<<<EE, 256>>>(Wg);
    gate_kernel<<<(BB * SS) / 128, 256, GATE_SM>>>(xmap, wgmap, bg);
    topk_gather_kernel<<<dim3(EE, BB), 256>>>(x);

    expert_mma<0><<<dim3(OO / 128, EE, SPLIT), 256, SM_TOTAL>>>(w1m, iph, ipl, KD);
    reduce_kernel<0><<<RED_GRID, 256>>>(b1, nullptr);

    expert_mma<1><<<dim3(OO / 128, EE, SPLIT), 256, SM_TOTAL>>>(w2m, h1h, h1l, OO);
    reduce_kernel<1><<<RED_GRID, 256>>>(b2, nullptr);

    expert_mma<2><<<dim3(OO / 128, EE, SPLIT), 256, SM_TOTAL>>>(w3m, h2h, h2l, OO);
    reduce_kernel<2><<<RED_GRID, 256>>>(b3, out);
}